// round 6
// baseline (speedup 1.0000x reference)
#include <cuda_runtime.h>
#include <math.h>

#define BB   32
#define LL   4096
#define DIN  32
#define HH   256
#define NN   32
#define DOUT 16
#define J1   128   // H/2

typedef unsigned long long ull;

// Scratch (device globals: allocation-free per harness rules)
__device__ float g_hrelu[BB*LL*J1];   // 64 MB
__device__ float g_kt[LL*HH];         // 4 MB: kt[m][h] = k[h][L-1-m] (+D[h] at m=L-1)
__device__ float g_part[BB*64*HH];    // 2 MB
__device__ float g_gel[BB*HH];        // gelu(y_last)
__device__ float g_glu[BB*HH];        // after GLU

// ---- packed f32x2 helpers (FFMA2: PTX-only, 2x fp32 FMA throughput) ----
__device__ __forceinline__ ull pack2(float x, float y) {
    ull r; asm("mov.b64 %0, {%1, %2};" : "=l"(r) : "f"(x), "f"(y)); return r;
}
__device__ __forceinline__ void fma2(ull& d, ull a, ull b) {
    asm("fma.rn.f32x2 %0, %1, %2, %0;" : "+l"(d) : "l"(a), "l"(b));
}
__device__ __forceinline__ ull add2(ull a, ull b) {
    ull r; asm("add.rn.f32x2 %0, %1, %2;" : "=l"(r) : "l"(a), "l"(b)); return r;
}
__device__ __forceinline__ float2 unpack2(ull v) {
    float2 f; asm("mov.b64 {%0, %1}, %2;" : "=f"(f.x), "=f"(f.y) : "l"(v)); return f;
}

// ---------------- kernel 1: hrelu = relu(data @ w1 + b1), f32x2 ----------------
// Block tile: 32 rows x 128 cols (=64 col-pairs), K=32. 256 threads, 2x4 f32x2/thread.
__global__ void __launch_bounds__(256) k_hrelu(const float* __restrict__ data,
                                               const float* __restrict__ w1,
                                               const float* __restrict__ b1) {
    __shared__ float sd[32][DIN];          // 4 KB
    __shared__ float2 sw[DIN*64];          // 16 KB (w1 as col-pairs)
    int tid = threadIdx.x;
    int row0 = blockIdx.x * 32;
    // load data tile: 1024 floats as 256 float4
    {
        int r = tid >> 3, q = tid & 7;
        float4 v = *reinterpret_cast<const float4*>(&data[(size_t)(row0 + r)*DIN + q*4]);
        sd[r][q*4+0] = v.x; sd[r][q*4+1] = v.y; sd[r][q*4+2] = v.z; sd[r][q*4+3] = v.w;
    }
    // load w1: 32x64 float2, 8 per thread
    const float2* w1f2 = reinterpret_cast<const float2*>(w1);
    #pragma unroll
    for (int t = 0; t < 8; t++) sw[tid + t*256] = w1f2[tid + t*256];
    __syncthreads();

    int tx = tid & 15, ty = tid >> 4;      // cols: tx+jp*16 (jp 0..3); rows: ty+i*16 (i 0..1)
    const float2* b1f2 = reinterpret_cast<const float2*>(b1);
    ull acc[2][4];
    #pragma unroll
    for (int jp = 0; jp < 4; jp++) {
        float2 bv = b1f2[tx + jp*16];
        ull bp = pack2(bv.x, bv.y);
        acc[0][jp] = bp; acc[1][jp] = bp;
    }
    #pragma unroll
    for (int k = 0; k < DIN; k++) {
        ull a0 = pack2(sd[ty][k],      sd[ty][k]);
        ull a1 = pack2(sd[ty+16][k],   sd[ty+16][k]);
        #pragma unroll
        for (int jp = 0; jp < 4; jp++) {
            ull wv = *reinterpret_cast<const ull*>(&sw[k*64 + tx + jp*16]);
            fma2(acc[0][jp], a0, wv);
            fma2(acc[1][jp], a1, wv);
        }
    }
    float2* outf2 = reinterpret_cast<float2*>(g_hrelu);
    #pragma unroll
    for (int i = 0; i < 2; i++) {
        size_t rowbase = (size_t)(row0 + ty + i*16) * 64;
        #pragma unroll
        for (int jp = 0; jp < 4; jp++) {
            float2 v = unpack2(acc[i][jp]);
            v.x = fmaxf(v.x, 0.f); v.y = fmaxf(v.y, 0.f);
            outf2[rowbase + tx + jp*16] = v;
        }
    }
}

// ---------------- kernel 2: SSM kernel k, reversed+transposed ----------------
// l-chunk of 16 per block (grid 256) for 2 blocks/SM -> hides recurrence chain.
__global__ void __launch_bounds__(256) k_kt(const float* __restrict__ log_dt,
                                            const float* __restrict__ A_re,
                                            const float* __restrict__ A_im,
                                            const float* __restrict__ C_re,
                                            const float* __restrict__ C_im,
                                            const float* __restrict__ Dv) {
    const int h  = threadIdx.x;
    const int l0 = blockIdx.x * 16;
    float acc[16];
    #pragma unroll
    for (int i = 0; i < 16; i++) acc[i] = 0.f;
    float dt = expf(log_dt[h]);
    for (int n = 0; n < NN; n++) {
        float are = A_re[h*NN+n], aim = A_im[h*NN+n];
        float dre = dt*are, dim = dt*aim;
        float er = expf(dre);
        float ws, wc; sincosf(dim, &ws, &wc);
        float wre = er*wc, wim = er*ws;                 // w = exp(dtA)
        float nre = wre - 1.f, nim = wim;
        float inv = 1.f/(are*are + aim*aim);
        float qre = (nre*are + nim*aim)*inv;
        float qim = (nim*are - nre*aim)*inv;
        float cre = C_re[h*NN+n], cim = C_im[h*NN+n];
        float kre = cre*qre - cim*qim;
        float kim = cre*qim + cim*qre;
        const double TWO_PI = 6.283185307179586476925286766559;
        double th = (double)dim * (double)l0;
        float thr = (float)(th - TWO_PI * rint(th * (1.0/TWO_PI)));
        float mag = expf(dre * (float)l0);
        float ps, pc; sincosf(thr, &ps, &pc);
        float pre = mag*pc, pim = mag*ps;
        #pragma unroll
        for (int i = 0; i < 16; i++) {
            acc[i] += kre*pre - kim*pim;
            float t = pre*wre - pim*wim;
            pim = pre*wim + pim*wre;
            pre = t;
        }
    }
    float dh = Dv[h];
    #pragma unroll
    for (int i = 0; i < 16; i++) {
        int l = l0 + i;
        float v = 2.f*acc[i];
        if (l == 0) v += dh;
        g_kt[(size_t)(LL-1-l)*HH + h] = v;
    }
}

// ---------------- kernel 3: fused hrelu@w2+b2 then dot with kt, f32x2 -------------
// Block tile: 64(m) x 256(h) -> grid.y=1, hrelu read exactly once.
// 256 threads, 4x8 f32x2 per thread. K chunk = 16.
#define KSTEP 16
__global__ void __launch_bounds__(256) k_gemm(const float* __restrict__ w2,
                                              const float* __restrict__ b2) {
    __shared__ float  As[KSTEP][72];       // 4.6 KB  (As[k][r])
    __shared__ float2 Ws[KSTEP][128];      // 16 KB   (Ws[k][col-pair])
    __shared__ ull    red2[128*17];        // 17.4 KB
    int tid = threadIdx.x;
    int tx = tid & 15, ty = tid >> 4;      // cols: tx+jp*16 (jp 0..7); rows: ty+i*16 (i 0..3)
    int row0 = blockIdx.x * 64;
    const float2* w2f2 = reinterpret_cast<const float2*>(w2);

    ull acc[4][8];
    #pragma unroll
    for (int i = 0; i < 4; i++)
        #pragma unroll
        for (int jp = 0; jp < 8; jp++) acc[i][jp] = 0ull;

    for (int k0 = 0; k0 < J1; k0 += KSTEP) {
        // As: 64 rows x 16 k -> 256 float4 loads, stored transposed
        {
            int r = tid >> 2, q = tid & 3;
            float4 v = *reinterpret_cast<const float4*>(
                &g_hrelu[(size_t)(row0 + r)*J1 + k0 + q*4]);
            As[q*4+0][r] = v.x; As[q*4+1][r] = v.y; As[q*4+2][r] = v.z; As[q*4+3][r] = v.w;
        }
        // Ws: 16 k x 128 col-pairs -> 8 float2 per thread
        #pragma unroll
        for (int t = 0; t < 8; t++) {
            int idx = tid + t*256;
            int kk = idx >> 7, cp = idx & 127;
            Ws[kk][cp] = w2f2[(size_t)(k0+kk)*128 + cp];
        }
        __syncthreads();
        #pragma unroll
        for (int kk = 0; kk < KSTEP; kk++) {
            ull aa[4];
            #pragma unroll
            for (int i = 0; i < 4; i++) {
                float a = As[kk][ty + i*16];
                aa[i] = pack2(a, a);
            }
            #pragma unroll
            for (int jp = 0; jp < 8; jp++) {
                ull wv = *reinterpret_cast<const ull*>(&Ws[kk][tx + jp*16]);
                #pragma unroll
                for (int i = 0; i < 4; i++) fma2(acc[i][jp], aa[i], wv);
            }
        }
        __syncthreads();
    }
    // epilogue: x = acc + b2; dot with kt over the 4 rows; tree-reduce over ty
    int b     = row0 >> 12;
    int mloc0 = row0 & 4095;
    const float2* b2f2 = reinterpret_cast<const float2*>(b2);
    const ull* ktu = reinterpret_cast<const ull*>(g_kt);
    #pragma unroll
    for (int jp = 0; jp < 8; jp++) {
        int cp = tx + jp*16;
        float2 bv = b2f2[cp];
        ull bp = pack2(bv.x, bv.y);
        ull part = 0ull;
        #pragma unroll
        for (int i = 0; i < 4; i++) {
            int m = mloc0 + ty + i*16;
            ull x = add2(acc[i][jp], bp);
            ull kv = ktu[(size_t)m*128 + cp];
            fma2(part, x, kv);
        }
        red2[cp*17 + ty] = part;
    }
    __syncthreads();
    if (tid < 128) {
        int cp = tid;
        float2 s = make_float2(0.f, 0.f);
        #pragma unroll
        for (int q = 0; q < 16; q++) {
            float2 v = unpack2(red2[cp*17 + q]);
            s.x += v.x; s.y += v.y;
        }
        int mblk = blockIdx.x & 63;
        reinterpret_cast<float2*>(g_part)[(size_t)(b*64 + mblk)*128 + cp] = s;
    }
}

// ---------------- kernel 4a: reduce partials + exact gelu ----------------
__global__ void __launch_bounds__(256) k_head_a() {
    int b = blockIdx.x, t = threadIdx.x;
    float y = 0.f;
    #pragma unroll 8
    for (int mb = 0; mb < 64; mb++) y += g_part[(size_t)(b*64 + mb)*HH + t];
    g_gel[b*HH + t] = 0.5f * y * (1.f + erff(y * 0.70710678118654752f));
}

// ---------------- kernel 4b: GLU: (g@Wg+bg) -> a*sigmoid(b) ----------------
__global__ void __launch_bounds__(128) k_head_b(const float* __restrict__ Wg,
                                                const float* __restrict__ bg) {
    __shared__ float gsh[HH];
    int b = blockIdx.x, t = blockIdx.y*128 + threadIdx.x;
    gsh[threadIdx.x]       = g_gel[b*HH + threadIdx.x];
    gsh[threadIdx.x + 128] = g_gel[b*HH + threadIdx.x + 128];
    __syncthreads();
    float a  = bg[t];
    float bs = bg[HH + t];
    #pragma unroll 8
    for (int h = 0; h < HH; h++) {
        float gv = gsh[h];
        a  += gv * Wg[(size_t)h*(2*HH) + t];
        bs += gv * Wg[(size_t)h*(2*HH) + HH + t];
    }
    g_glu[b*HH + t] = a / (1.f + expf(-bs));
}

// ---------------- kernel 4c: z = relu(glu@w3+b3); out = z@w4+b4 ----------------
__global__ void __launch_bounds__(128) k_head_c(const float* __restrict__ w3,
                                                const float* __restrict__ b3,
                                                const float* __restrict__ w4,
                                                const float* __restrict__ b4,
                                                float* __restrict__ out) {
    __shared__ float glu[HH];
    __shared__ float zsh[J1];
    int b = blockIdx.x, t = threadIdx.x;
    glu[t]       = g_glu[b*HH + t];
    glu[t + 128] = g_glu[b*HH + t + 128];
    __syncthreads();
    float z = b3[t];
    #pragma unroll 8
    for (int h = 0; h < HH; h++) z += glu[h] * w3[(size_t)h*J1 + t];
    zsh[t] = fmaxf(z, 0.f);
    __syncthreads();
    if (t < DOUT) {
        float o = b4[t];
        #pragma unroll 8
        for (int j = 0; j < J1; j++) o += zsh[j] * w4[j*DOUT + t];
        out[b*DOUT + t] = o;
    }
}

extern "C" void kernel_launch(void* const* d_in, const int* in_sizes, int n_in,
                              void* d_out, int out_size) {
    const float* data   = (const float*)d_in[0];
    const float* w1     = (const float*)d_in[1];
    const float* b1     = (const float*)d_in[2];
    const float* w2     = (const float*)d_in[3];
    const float* b2     = (const float*)d_in[4];
    const float* log_dt = (const float*)d_in[5];
    const float* A_re   = (const float*)d_in[6];
    const float* A_im   = (const float*)d_in[7];
    const float* C_re   = (const float*)d_in[8];
    const float* C_im   = (const float*)d_in[9];
    const float* Dv     = (const float*)d_in[10];
    const float* Wg     = (const float*)d_in[11];
    const float* bg     = (const float*)d_in[12];
    const float* w3     = (const float*)d_in[13];
    const float* b3     = (const float*)d_in[14];
    const float* w4     = (const float*)d_in[15];
    const float* b4     = (const float*)d_in[16];
    float* out = (float*)d_out;

    k_kt<<<LL/16, 256>>>(log_dt, A_re, A_im, C_re, C_im, Dv);
    k_hrelu<<<BB*LL/32, 256>>>(data, w1, b1);
    k_gemm<<<BB*LL/64, 256>>>(w2, b2);
    k_head_a<<<BB, 256>>>();
    k_head_b<<<dim3(BB, 2), 128>>>(Wg, bg);
    k_head_c<<<BB, 128>>>(w3, b3, w4, b4, out);
}